// round 12
// baseline (speedup 1.0000x reference)
#include <cuda_runtime.h>
#include <cuda_bf16.h>
#include <cstdint>
#include <cstddef>

// ---------------------------------------------------------------------------
// 2-layer LSTM, B=32, T=512, I=H=1024, fp32 I/O.
// ldmatrix + mma.sync.m16n8k16.bf16.f32, Markidis split:
// D = WhiChi + WhiClo + WloChi, fp32 accum.
// 128 CTAs x 512 thr wavefront (layer0 @ s, layer1 @ s-1), 513 steps.
// Per CTA/step: D[64 rows x 32 batch], K=2048 = 16 stages x 128k.
// 4-slot smem ring (48KB/slot), prefetch distance 3, cp_wait<2> steady state,
// one __syncthreads per stage. 16 warps = 2 row-groups(32r) x 8 k-splits(16k);
// per warp-stage: 8 ldmatrix.x4 + 24 mma, loop-invariant addresses.
// Weight stage 0/1 prefetched pre-grid-barrier (weights step-invariant).
// ---------------------------------------------------------------------------

#define NCTA 128
#define NTHR 512
#define TSTEPS 512
#define SLOT 49152u
#define SMEM_BYTES (4 * 49152)

__device__ __align__(16) unsigned char g_Whi[2u*64u*16u*16384u];  // 32 MB
__device__ __align__(16) unsigned char g_Wlo[2u*64u*16u*16384u];  // 32 MB
__device__ __align__(16) unsigned char g_xhi[512u*8u*8192u];      // 32 MB
__device__ __align__(16) unsigned char g_xlo[512u*8u*8192u];      // 32 MB
__device__ __align__(16) unsigned char g_h0hi[2*8*8192];
__device__ __align__(16) unsigned char g_h0lo[2*8*8192];
__device__ __align__(16) unsigned char g_h1hi[2*8*8192];
__device__ __align__(16) unsigned char g_h1lo[2*8*8192];
__device__ unsigned g_bar_count;
__device__ volatile unsigned g_bar_gen;

__device__ __forceinline__ void cpa16(uint32_t d, const void* s) {
    asm volatile("cp.async.cg.shared.global [%0], [%1], 16;" :: "r"(d), "l"(s));
}
__device__ __forceinline__ void cp_commit() { asm volatile("cp.async.commit_group;"); }
template<int N> __device__ __forceinline__ void cp_wait() {
    asm volatile("cp.async.wait_group %0;" :: "n"(N));
}
#define LDSM4(R, A) \
    asm volatile("ldmatrix.sync.aligned.m8n8.x4.shared.b16 {%0,%1,%2,%3}, [%4];" \
        : "=r"((R)[0]), "=r"((R)[1]), "=r"((R)[2]), "=r"((R)[3]) : "r"(A))
#define MMA(D, A, B0, B1) \
    asm volatile("mma.sync.aligned.m16n8k16.row.col.f32.bf16.bf16.f32 " \
        "{%0,%1,%2,%3}, {%4,%5,%6,%7}, {%8,%9}, {%0,%1,%2,%3};" \
        : "+f"((D)[0]), "+f"((D)[1]), "+f"((D)[2]), "+f"((D)[3]) \
        : "r"((A)[0]), "r"((A)[1]), "r"((A)[2]), "r"((A)[3]), "r"(B0), "r"(B1))

__device__ __forceinline__ void grid_bar() {
    __syncthreads();
    if (threadIdx.x == 0) {
        __threadfence();
        unsigned gen = g_bar_gen;
        if (atomicAdd(&g_bar_count, 1u) == NCTA - 1) {
            g_bar_count = 0; __threadfence(); g_bar_gen = gen + 1;
        } else { while (g_bar_gen == gen) { __nanosleep(32); } }
        __threadfence();
    }
    __syncthreads();
}

__device__ __forceinline__ void split_bf16(float v, unsigned short* hi,
                                           unsigned short* lo) {
    __nv_bfloat16 h = __float2bfloat16_rn(v);
    __nv_bfloat16 l = __float2bfloat16_rn(v - __bfloat162float(h));
    *hi = __bfloat16_as_ushort(h);
    *lo = __bfloat16_as_ushort(l);
}

// ---- prep: per-(cta,stage) swizzled W images (64 rows x 128 k, 16KB) ----
extern "C" __global__ void prep_w(const float* __restrict__ W0,
                                  const float* __restrict__ W1) {
    unsigned m = blockIdx.x * 512u + threadIdx.x;     // < 2^21
    unsigned p = m & 1023u, st = (m >> 10) & 15u;
    unsigned mblk = (m >> 14) & 63u, l = (m >> 20) & 1u;
    unsigned r = p >> 4, c16 = (p & 15u) ^ (r & 7u);
    const float* W = l ? W1 : W0;
    unsigned grow = (r >> 4) * 1024u + mblk * 16u + (r & 15u);
    const float* src = W + (size_t)grow * 2048 + st * 128 + c16 * 8;
    union { unsigned short us[8]; uint4 q; } hq, lq;
    #pragma unroll
    for (int e = 0; e < 8; ++e) split_bf16(src[e], &hq.us[e], &lq.us[e]);
    size_t base = ((size_t)(l * 64u + mblk) * 16u + st) * 16384u + p * 16u;
    *(uint4*)(g_Whi + base) = hq.q;
    *(uint4*)(g_Wlo + base) = lq.q;
}
// ---- prep: per-(t,stage) swizzled x images (32 b x 128 k, 8KB) ----
extern "C" __global__ void prep_x(const float* __restrict__ x) {
    unsigned m = blockIdx.x * 512u + threadIdx.x;     // < 2^21
    unsigned p = m & 511u, st = (m >> 9) & 7u, t = (m >> 12) & 511u;
    unsigned b = p >> 4, c16 = (p & 15u) ^ (b & 7u);
    const float* src = x + (size_t)b * 524288 + (size_t)t * 1024 + st * 128 + c16 * 8;
    union { unsigned short us[8]; uint4 q; } hq, lq;
    #pragma unroll
    for (int e = 0; e < 8; ++e) split_bf16(src[e], &hq.us[e], &lq.us[e]);
    size_t base = ((size_t)t * 8u + st) * 8192u + p * 16u;
    *(uint4*)(g_xhi + base) = hq.q;
    *(uint4*)(g_xlo + base) = lq.q;
}
extern "C" __global__ void prep_zero() {
    unsigned i = blockIdx.x * 512u + threadIdx.x;     // < 32768
    ((unsigned*)g_h0hi)[i] = 0u; ((unsigned*)g_h0lo)[i] = 0u;
    ((unsigned*)g_h1hi)[i] = 0u; ((unsigned*)g_h1lo)[i] = 0u;
}

// ---- main persistent kernel ----
extern "C" __global__ void __launch_bounds__(NTHR, 1)
lstm_mma(const float* __restrict__ b0, const float* __restrict__ b1,
         float* __restrict__ out)
{
    extern __shared__ char sm[];
    const uint32_t sb = (uint32_t)__cvta_generic_to_shared(sm);
    float* gs = (float*)(sm + 2 * SLOT);   // overlays slots 2,3: [8][64][34]

    const int tid = threadIdx.x, cta = blockIdx.x;
    const int l = cta >> 6, mblk = cta & 63;
    const int wv = tid >> 5, lane = tid & 31;
    const int rg = wv & 1, ksplit = wv >> 1;        // 2 row-groups x 8 k-splits
    const uint32_t lx7 = lane & 7;
    const uint32_t c0 = (uint32_t)(ksplit * 2);     // k16 chunk pair base
    const uint32_t acb = (lane >> 4) & 1, bcb = (lane >> 3) & 1;
    const uint32_t Aoff = (uint32_t)(rg * 32 + (lane & 15)) * 256u
                        + (((c0 + acb) ^ lx7) << 4);
    const uint32_t Boff = (uint32_t)((lane & 7) + ((lane >> 4) << 3)) * 256u
                        + (((c0 + bcb) ^ lx7) << 4);

    // pointwise item
    const int pj = tid & 15, pb = tid >> 4;
    const int n = mblk * 16 + pj;

    const float* bias = l ? b1 : b0;
    float br[4];
    #pragma unroll
    for (int g = 0; g < 4; ++g) br[g] = bias[g * 1024 + n];
    float cst = 0.f;
    const size_t wbase = (size_t)cta * 262144u;     // 16 images * 16KB

    // fetch weights for 128k stage st into slot st&3 (32KB)
    auto fetch_w = [&](int st) {
        uint32_t buf = sb + (uint32_t)(st & 3) * SLOT;
        const unsigned char* wh = g_Whi + wbase + (size_t)st * 16384u;
        const unsigned char* wl = g_Wlo + wbase + (size_t)st * 16384u;
        cpa16(buf + tid * 16,          wh + tid * 16);
        cpa16(buf + 8192u + tid * 16,  wh + 8192 + tid * 16);
        cpa16(buf + 16384u + tid * 16, wl + tid * 16);
        cpa16(buf + 24576u + tid * 16, wl + 8192 + tid * 16);
    };
    // fetch activations for stage st (16KB)
    auto fetch_c = [&](int st, int t, int rp) {
        uint32_t buf = sb + (uint32_t)(st & 3) * SLOT;
        const unsigned char *ch, *cl;
        if (l == 0) {
            if (st < 8) { ch = g_xhi + ((size_t)t * 8 + st) * 8192u;
                          cl = g_xlo + ((size_t)t * 8 + st) * 8192u; }
            else        { ch = g_h0hi + (rp * 8 + st - 8) * 8192;
                          cl = g_h0lo + (rp * 8 + st - 8) * 8192; }
        } else {
            if (st < 8) { ch = g_h0hi + (rp * 8 + st) * 8192;
                          cl = g_h0lo + (rp * 8 + st) * 8192; }
            else        { ch = g_h1hi + (rp * 8 + st - 8) * 8192;
                          cl = g_h1lo + (rp * 8 + st - 8) * 8192; }
        }
        cpa16(buf + 32768u + tid * 16, ch + tid * 16);
        cpa16(buf + 40960u + tid * 16, cl + tid * 16);
    };

    // first step's stage-0/1 weights prefetched before the initial barrier (G1)
    if (l == 0) { fetch_w(0); fetch_w(1); cp_commit(); }
    grid_bar();                                      // preps visible chip-wide

    #pragma unroll 1
    for (int s = 0; s <= TSTEPS; ++s) {
        const bool active = l ? (s >= 1) : (s < TSTEPS);
        if (active) {
            const int t = l ? (s - 1) : s;
            const int rp = (s + 1) & 1, wp = s & 1;

            fetch_c(0, t, rp); fetch_c(1, t, rp); cp_commit();   // G2
            fetch_w(2); fetch_c(2, t, rp); cp_commit();          // G3

            float d[2][4][4];
            #pragma unroll
            for (int mt = 0; mt < 2; ++mt)
                #pragma unroll
                for (int j = 0; j < 4; ++j)
                    #pragma unroll
                    for (int e = 0; e < 4; ++e) d[mt][j][e] = 0.f;

            #pragma unroll 1
            for (int st = 0; st < 16; ++st) {
                // stage st's data lives in: st<2 -> G1/G2; st>=2 -> G(st+1)
                if (st == 0 || st == 14) cp_wait<1>();
                else if (st == 15)       cp_wait<0>();
                else                     cp_wait<2>();
                __syncthreads();     // copies visible; slot (st+3)&3 readers done
                if (st <= 12) { fetch_w(st + 3); fetch_c(st + 3, t, rp); cp_commit(); }

                const uint32_t buf = sb + (uint32_t)(st & 3) * SLOT;
                uint32_t AH0[4], AH1[4], AL0[4], AL1[4];
                uint32_t BH0[4], BH1[4], BL0[4], BL1[4];
                LDSM4(AH0, buf + Aoff);
                LDSM4(AH1, buf + Aoff + 4096u);
                LDSM4(AL0, buf + 16384u + Aoff);
                LDSM4(AL1, buf + 16384u + Aoff + 4096u);
                LDSM4(BH0, buf + 32768u + Boff);
                LDSM4(BH1, buf + 32768u + Boff + 4096u);
                LDSM4(BL0, buf + 40960u + Boff);
                LDSM4(BL1, buf + 40960u + Boff + 4096u);
                #pragma unroll
                for (int mt = 0; mt < 2; ++mt) {
                    uint32_t* ah = mt ? AH1 : AH0;
                    uint32_t* al = mt ? AL1 : AL0;
                    #pragma unroll
                    for (int j = 0; j < 4; ++j) {
                        uint32_t* bh = (j & 2) ? BH1 : BH0;
                        uint32_t* bl = (j & 2) ? BL1 : BL0;
                        const int o = (j & 1) * 2;
                        MMA(d[mt][j], ah, bh[o], bh[o + 1]);
                        MMA(d[mt][j], ah, bl[o], bl[o + 1]);
                        MMA(d[mt][j], al, bh[o], bh[o + 1]);
                    }
                }
            }
            __syncthreads();           // slots 2,3 reads done -> gs overlay safe

            // ---- partial sums -> gs[8][64][34] ----
            {
                float* slab = gs + ksplit * 2176;
                #pragma unroll
                for (int mt = 0; mt < 2; ++mt) {
                    const int r1 = rg * 32 + mt * 16 + (lane >> 2);
                    #pragma unroll
                    for (int j = 0; j < 4; ++j) {
                        const int c = j * 8 + 2 * (lane & 3);
                        *(float2*)&slab[r1 * 34 + c] =
                            make_float2(d[mt][j][0], d[mt][j][1]);
                        *(float2*)&slab[(r1 + 8) * 34 + c] =
                            make_float2(d[mt][j][2], d[mt][j][3]);
                    }
                }
            }
            __syncthreads();

            // ---- pointwise: thread owns (neuron pj, batch pb) ----
            float gsum[4];
            #pragma unroll
            for (int g = 0; g < 4; ++g) {
                const int row = g * 16 + pj;
                float v = 0.f;
                #pragma unroll
                for (int ks = 0; ks < 8; ++ks)
                    v += gs[ks * 2176 + row * 34 + pb];
                gsum[g] = v + br[g];
            }
            float fg = 1.f / (1.f + expf(-gsum[0]));
            float ig = 1.f / (1.f + expf(-gsum[1]));
            float og = 1.f / (1.f + expf(-gsum[3]));
            float c = fg * cst + ig * tanhf(gsum[2]);
            cst = c;
            float h = og * tanhf(c);

            unsigned short hh, hl;
            split_bf16(h, &hh, &hl);
            const int st8 = n >> 7, c16 = (n >> 3) & 15, i8 = n & 7;
            size_t off = (size_t)(wp * 8 + st8) * 8192u + pb * 256u
                       + (unsigned)((c16 ^ (pb & 7)) * 16) + i8 * 2u;
            if (l == 0) {
                *(unsigned short*)(g_h0hi + off) = hh;
                *(unsigned short*)(g_h0lo + off) = hl;
            } else {
                *(unsigned short*)(g_h1hi + off) = hh;
                *(unsigned short*)(g_h1lo + off) = hl;
                out[(size_t)pb * 524288 + (size_t)t * 1024 + n] = h;
            }
            if (t == TSTEPS - 1) {
                out[16777216 + l * 32768 + pb * 1024 + n] = h;   // h_n
                out[16842752 + l * 32768 + pb * 1024 + n] = c;   // c_n
            }
        }

        // prefetch next step's stage-0/1 weights (slots 0,1) before the barrier
        const bool nxt = l ? (s < TSTEPS) : (s + 1 < TSTEPS);
        if (nxt) { fetch_w(0); fetch_w(1); cp_commit(); }        // next G1
        grid_bar();
    }
}

extern "C" void kernel_launch(void* const* d_in, const int* in_sizes, int n_in,
                              void* d_out, int out_size)
{
    (void)in_sizes; (void)n_in; (void)out_size;
    const float* x  = (const float*)d_in[0];
    const float* W0 = (const float*)d_in[1];
    const float* b0 = (const float*)d_in[2];
    const float* W1 = (const float*)d_in[3];
    const float* b1 = (const float*)d_in[4];

    prep_w<<<4096, 512>>>(W0, W1);
    prep_x<<<4096, 512>>>(x);
    prep_zero<<<64, 512>>>();

    cudaFuncSetAttribute(lstm_mma,
                         cudaFuncAttributeMaxDynamicSharedMemorySize, SMEM_BYTES);
    lstm_mma<<<NCTA, NTHR, SMEM_BYTES>>>(b0, b1, (float*)d_out);
}

// round 13
// speedup vs baseline: 1.3460x; 1.3460x over previous
#include <cuda_runtime.h>
#include <cuda_bf16.h>
#include <cstdint>
#include <cstddef>

// ---------------------------------------------------------------------------
// 2-layer LSTM, B=32, T=512, I=H=1024, fp32 I/O.
// ldmatrix + mma.sync.m16n8k16.bf16.f32, Markidis split:
// D = WhiChi + WhiClo + WloChi, fp32 accum.
// 128 CTAs x 512 thr wavefront (layer0 @ s, layer1 @ s-1), 513 steps.
// Per CTA/step: D[64 rows x 32 batch], K=2048 = 16 stages x 128k.
// WARP-PAIR-PRIVATE pipelines: 8 pairs (2 warps sharing B), each with its own
// 4-slot x 6KB smem ring + cp.async chain; per-stage sync = bar.sync(id,64)
// only. Global images pair-sliced (contiguous per (stage,pair)) with a
// conflict-free 32B-row swizzle. gs epilogue overlays each pair's slots 2-3.
// ---------------------------------------------------------------------------

#define NCTA 128
#define NTHR 512
#define TSTEPS 512
#define PRING 24576u              // 4 slots x 6KB per pair
#define SMEM_BYTES (8 * 24576)    // 196608

__device__ __align__(16) unsigned char g_Whi[2u*64u*16u*8u*2048u];  // 32 MB
__device__ __align__(16) unsigned char g_Wlo[2u*64u*16u*8u*2048u];  // 32 MB
__device__ __align__(16) unsigned char g_xhi[512u*8u*8u*1024u];     // 32 MB
__device__ __align__(16) unsigned char g_xlo[512u*8u*8u*1024u];     // 32 MB
__device__ __align__(16) unsigned char g_h0hi[2*8*8*1024];
__device__ __align__(16) unsigned char g_h0lo[2*8*8*1024];
__device__ __align__(16) unsigned char g_h1hi[2*8*8*1024];
__device__ __align__(16) unsigned char g_h1lo[2*8*8*1024];
__device__ unsigned g_bar_count;
__device__ volatile unsigned g_bar_gen;

__device__ __forceinline__ void cpa16(uint32_t d, const void* s) {
    asm volatile("cp.async.cg.shared.global [%0], [%1], 16;" :: "r"(d), "l"(s));
}
__device__ __forceinline__ void cp_commit() { asm volatile("cp.async.commit_group;"); }
template<int N> __device__ __forceinline__ void cp_wait() {
    asm volatile("cp.async.wait_group %0;" :: "n"(N));
}
#define LDSM4(R, A) \
    asm volatile("ldmatrix.sync.aligned.m8n8.x4.shared.b16 {%0,%1,%2,%3}, [%4];" \
        : "=r"((R)[0]), "=r"((R)[1]), "=r"((R)[2]), "=r"((R)[3]) : "r"(A))
#define MMA(D, A, B0, B1) \
    asm volatile("mma.sync.aligned.m16n8k16.row.col.f32.bf16.bf16.f32 " \
        "{%0,%1,%2,%3}, {%4,%5,%6,%7}, {%8,%9}, {%0,%1,%2,%3};" \
        : "+f"((D)[0]), "+f"((D)[1]), "+f"((D)[2]), "+f"((D)[3]) \
        : "r"((A)[0]), "r"((A)[1]), "r"((A)[2]), "r"((A)[3]), "r"(B0), "r"(B1))

__device__ __forceinline__ void grid_bar() {
    __syncthreads();
    if (threadIdx.x == 0) {
        __threadfence();
        unsigned gen = g_bar_gen;
        if (atomicAdd(&g_bar_count, 1u) == NCTA - 1) {
            g_bar_count = 0; __threadfence(); g_bar_gen = gen + 1;
        } else { while (g_bar_gen == gen) { __nanosleep(32); } }
        __threadfence();
    }
    __syncthreads();
}

__device__ __forceinline__ void split_bf16(float v, unsigned short* hi,
                                           unsigned short* lo) {
    __nv_bfloat16 h = __float2bfloat16_rn(v);
    __nv_bfloat16 l = __float2bfloat16_rn(v - __bfloat162float(h));
    *hi = __bfloat16_as_ushort(h);
    *lo = __bfloat16_as_ushort(l);
}

// intra-slice swizzled byte offset for element (row, seg, e): rows are 32B
// (16 bf16), two 16B segs per row, seg bit XORed with row>>2 for bank spread
__device__ __forceinline__ unsigned sloff(unsigned row, unsigned seg) {
    return row * 32u + (((seg ^ (row >> 2)) & 1u) << 4);
}

// ---- prep: W -> pair-sliced images [l][cta64][st16][pair8][2KB] ----
extern "C" __global__ void prep_w(const float* __restrict__ W0,
                                  const float* __restrict__ W1) {
    unsigned m = blockIdx.x * 512u + threadIdx.x;     // < 2^21
    unsigned c = m & 127u, pair = (m >> 7) & 7u, st = (m >> 10) & 15u;
    unsigned mblk = (m >> 14) & 63u, l = (m >> 20) & 1u;
    unsigned row = c >> 1, sp = c & 1;
    unsigned seg = sp ^ ((row >> 2) & 1u);            // logical k-seg
    const float* W = l ? W1 : W0;
    unsigned grow = (row >> 4) * 1024u + mblk * 16u + (row & 15u);
    unsigned k = st * 128u + pair * 16u + seg * 8u;
    const float* src = W + (size_t)grow * 2048 + k;
    union { unsigned short us[8]; uint4 q; } hq, lq;
    #pragma unroll
    for (int e = 0; e < 8; ++e) split_bf16(src[e], &hq.us[e], &lq.us[e]);
    size_t base = ((((size_t)(l * 64u + mblk) * 16u + st) * 8u + pair) * 2048u)
                + c * 16u;
    *(uint4*)(g_Whi + base) = hq.q;
    *(uint4*)(g_Wlo + base) = lq.q;
}
// ---- prep: x -> pair-sliced images [t][st8][pair8][1KB] ----
extern "C" __global__ void prep_x(const float* __restrict__ x) {
    unsigned m = blockIdx.x * 512u + threadIdx.x;     // < 2^21
    unsigned c = m & 63u, pair = (m >> 6) & 7u, st = (m >> 9) & 7u;
    unsigned t = m >> 12;
    unsigned row = c >> 1, sp = c & 1;                // row = batch
    unsigned seg = sp ^ ((row >> 2) & 1u);
    unsigned k = st * 128u + pair * 16u + seg * 8u;
    const float* src = x + (size_t)row * 524288 + (size_t)t * 1024 + k;
    union { unsigned short us[8]; uint4 q; } hq, lq;
    #pragma unroll
    for (int e = 0; e < 8; ++e) split_bf16(src[e], &hq.us[e], &lq.us[e]);
    size_t base = (((size_t)t * 8u + st) * 8u + pair) * 1024u + c * 16u;
    *(uint4*)(g_xhi + base) = hq.q;
    *(uint4*)(g_xlo + base) = lq.q;
}
extern "C" __global__ void prep_zero() {
    unsigned i = blockIdx.x * 512u + threadIdx.x;     // < 32768
    ((unsigned*)g_h0hi)[i] = 0u; ((unsigned*)g_h0lo)[i] = 0u;
    ((unsigned*)g_h1hi)[i] = 0u; ((unsigned*)g_h1lo)[i] = 0u;
}

// ---- main persistent kernel ----
extern "C" __global__ void __launch_bounds__(NTHR, 1)
lstm_mma(const float* __restrict__ b0, const float* __restrict__ b1,
         float* __restrict__ out)
{
    extern __shared__ char sm[];
    const uint32_t sb = (uint32_t)__cvta_generic_to_shared(sm);

    const int tid = threadIdx.x, cta = blockIdx.x;
    const int l = cta >> 6, mblk = cta & 63;
    const int wv = tid >> 5, lane = tid & 31;
    const int p = wv >> 1, rg = wv & 1;               // pair, row-group
    const int t64 = tid & 63;                         // thread-in-pair
    const uint32_t pbase = sb + (uint32_t)p * PRING;

    // LDSM lane addresses (loop-invariant; same fragment semantics as R11)
    const unsigned rowa0 = rg * 32 + (lane & 15), rowa1 = rowa0 + 16;
    const unsigned sega  = (lane >> 4) & 1;
    const uint32_t offA0 = sloff(rowa0, sega), offA1 = sloff(rowa1, sega);
    const unsigned rowb0 = (lane & 7) + ((lane >> 4) << 3), rowb1 = rowb0 + 16;
    const unsigned segb  = (lane >> 3) & 1;
    const uint32_t offB0 = sloff(rowb0, segb), offB1 = sloff(rowb1, segb);

    // pointwise item
    const int pj = tid & 15, pb = tid >> 4;
    const int n = mblk * 16 + pj;

    const float* bias = l ? b1 : b0;
    float br[4];
    #pragma unroll
    for (int g = 0; g < 4; ++g) br[g] = bias[g * 1024 + n];
    float cst = 0.f;

    const unsigned char* wHbase = g_Whi + (size_t)cta * 262144u;
    const unsigned char* wLbase = g_Wlo + (size_t)cta * 262144u;

    grid_bar();                                        // preps visible

    #pragma unroll 1
    for (int s = 0; s <= TSTEPS; ++s) {
        const bool active = l ? (s >= 1) : (s < TSTEPS);
        if (active) {
            const int t = l ? (s - 1) : s;
            const int rp = (s + 1) & 1, wp = s & 1;

            auto fetch = [&](int st) {
                uint32_t slot = pbase + (uint32_t)(st & 3) * 6144u;
                const unsigned char* wh = wHbase + (size_t)(st * 8 + p) * 2048u;
                const unsigned char* wl = wLbase + (size_t)(st * 8 + p) * 2048u;
                cpa16(slot + t64 * 16,         wh + t64 * 16);
                cpa16(slot + 1024 + t64 * 16,  wh + 1024 + t64 * 16);
                cpa16(slot + 2048 + t64 * 16,  wl + t64 * 16);
                cpa16(slot + 3072 + t64 * 16,  wl + 1024 + t64 * 16);
                const unsigned char *ch, *cl;
                if (l == 0) {
                    if (st < 8) {
                        ch = g_xhi + (((size_t)t * 8 + st) * 8 + p) * 1024u;
                        cl = g_xlo + (((size_t)t * 8 + st) * 8 + p) * 1024u;
                    } else {
                        ch = g_h0hi + ((rp * 8 + st - 8) * 8 + p) * 1024;
                        cl = g_h0lo + ((rp * 8 + st - 8) * 8 + p) * 1024;
                    }
                } else {
                    if (st < 8) {
                        ch = g_h0hi + ((rp * 8 + st) * 8 + p) * 1024;
                        cl = g_h0lo + ((rp * 8 + st) * 8 + p) * 1024;
                    } else {
                        ch = g_h1hi + ((rp * 8 + st - 8) * 8 + p) * 1024;
                        cl = g_h1lo + ((rp * 8 + st - 8) * 8 + p) * 1024;
                    }
                }
                cpa16(slot + 4096 + t64 * 16, ch + t64 * 16);
                cpa16(slot + 5120 + t64 * 16, cl + t64 * 16);
                cp_commit();
            };

            fetch(0); fetch(1); fetch(2);

            float d[2][4][4];
            #pragma unroll
            for (int mt = 0; mt < 2; ++mt)
                #pragma unroll
                for (int j = 0; j < 4; ++j)
                    #pragma unroll
                    for (int e = 0; e < 4; ++e) d[mt][j][e] = 0.f;

            #pragma unroll 1
            for (int st = 0; st < 16; ++st) {
                if (st <= 13)      cp_wait<2>();
                else if (st == 14) cp_wait<1>();
                else               cp_wait<0>();
                asm volatile("bar.sync %0, 64;" :: "r"(p + 1) : "memory");
                if (st <= 12) fetch(st + 3);

                const uint32_t slot = pbase + (uint32_t)(st & 3) * 6144u;
                uint32_t AH0[4], AH1[4], AL0[4], AL1[4];
                uint32_t BH0[4], BH1[4], BL0[4], BL1[4];
                LDSM4(AH0, slot + offA0);
                LDSM4(AH1, slot + offA1);
                LDSM4(AL0, slot + 2048u + offA0);
                LDSM4(AL1, slot + 2048u + offA1);
                LDSM4(BH0, slot + 4096u + offB0);
                LDSM4(BH1, slot + 4096u + offB1);
                LDSM4(BL0, slot + 5120u + offB0);
                LDSM4(BL1, slot + 5120u + offB1);
                #pragma unroll
                for (int mt = 0; mt < 2; ++mt) {
                    uint32_t* ah = mt ? AH1 : AH0;
                    uint32_t* al = mt ? AL1 : AL0;
                    #pragma unroll
                    for (int j = 0; j < 4; ++j) {
                        uint32_t* bh = (j & 2) ? BH1 : BH0;
                        uint32_t* bl = (j & 2) ? BL1 : BL0;
                        const int o = (j & 1) * 2;
                        MMA(d[mt][j], ah, bh[o], bh[o + 1]);
                        MMA(d[mt][j], ah, bl[o], bl[o + 1]);
                        MMA(d[mt][j], al, bh[o], bh[o + 1]);
                    }
                }
            }
            // partner must finish stage-15 reads before slab overlays slot 2/3
            asm volatile("bar.sync %0, 64;" :: "r"(p + 1) : "memory");

            // ---- partial sums -> per-pair slab (overlays own slots 2,3) ----
            {
                float* slab = (float*)(sm + p * PRING + 12288u);
                #pragma unroll
                for (int mt = 0; mt < 2; ++mt) {
                    const int r1 = rg * 32 + mt * 16 + (lane >> 2);
                    #pragma unroll
                    for (int j = 0; j < 4; ++j) {
                        const int c = j * 8 + 2 * (lane & 3);
                        *(float2*)&slab[r1 * 34 + c] =
                            make_float2(d[mt][j][0], d[mt][j][1]);
                        *(float2*)&slab[(r1 + 8) * 34 + c] =
                            make_float2(d[mt][j][2], d[mt][j][3]);
                    }
                }
            }
            __syncthreads();

            // ---- pointwise: thread owns (neuron pj, batch pb) ----
            float gsum[4];
            #pragma unroll
            for (int g = 0; g < 4; ++g) {
                const int row = g * 16 + pj;
                float v = 0.f;
                #pragma unroll
                for (int ks = 0; ks < 8; ++ks)
                    v += ((float*)(sm + ks * PRING + 12288u))[row * 34 + pb];
                gsum[g] = v + br[g];
            }
            float fg = 1.f / (1.f + expf(-gsum[0]));
            float ig = 1.f / (1.f + expf(-gsum[1]));
            float og = 1.f / (1.f + expf(-gsum[3]));
            float c = fg * cst + ig * tanhf(gsum[2]);
            cst = c;
            float h = og * tanhf(c);

            // write h as bf16 hi/lo into the pair-sliced h images
            unsigned short hh, hl;
            split_bf16(h, &hh, &hl);
            const unsigned stc = (unsigned)n >> 7, pr = ((unsigned)n >> 4) & 7u;
            const unsigned seg = ((unsigned)n >> 3) & 1u, e = (unsigned)n & 7u;
            size_t off = ((size_t)(wp * 8 + stc) * 8 + pr) * 1024u
                       + sloff((unsigned)pb, seg) + e * 2u;
            if (l == 0) {
                *(unsigned short*)(g_h0hi + off) = hh;
                *(unsigned short*)(g_h0lo + off) = hl;
            } else {
                *(unsigned short*)(g_h1hi + off) = hh;
                *(unsigned short*)(g_h1lo + off) = hl;
                out[(size_t)pb * 524288 + (size_t)t * 1024 + n] = h;
            }
            if (t == TSTEPS - 1) {
                out[16777216 + l * 32768 + pb * 1024 + n] = h;   // h_n
                out[16842752 + l * 32768 + pb * 1024 + n] = c;   // c_n
            }
        }
        grid_bar();
    }
}

extern "C" void kernel_launch(void* const* d_in, const int* in_sizes, int n_in,
                              void* d_out, int out_size)
{
    (void)in_sizes; (void)n_in; (void)out_size;
    const float* x  = (const float*)d_in[0];
    const float* W0 = (const float*)d_in[1];
    const float* b0 = (const float*)d_in[2];
    const float* W1 = (const float*)d_in[3];
    const float* b1 = (const float*)d_in[4];

    prep_w<<<4096, 512>>>(W0, W1);
    prep_x<<<4096, 512>>>(x);
    prep_zero<<<64, 512>>>();

    cudaFuncSetAttribute(lstm_mma,
                         cudaFuncAttributeMaxDynamicSharedMemorySize, SMEM_BYTES);
    lstm_mma<<<NCTA, NTHR, SMEM_BYTES>>>(b0, b1, (float*)d_out);
}